// round 10
// baseline (speedup 1.0000x reference)
#include <cuda_runtime.h>
#include <cuda_bf16.h>

// Problem constants
// B=8, N=2048, NP=1024, FN=6, FS=3, H=32, NQ=128
#define NB   8
#define NN   2048
#define NP_  1024
#define H_   32

// ---------------- scratch (device globals; no allocation) ----------------
__device__ float g_Ycat[NB * NN * 288];   // layer-1 right operands (9 x 32 cols)
__device__ float g_Z   [NB * NN * 288];   // layer-1 relu outputs x11,x12,x13,xb0..xb5
__device__ float g_Yp  [NB * NP_ * 32];   // x_p @ W_l1a[3]
__device__ float g_U   [NB * NN * 352];   // layer-2 right operands (raw order)
__device__ float g_pooled[NB * 32];       // sum over nodes of relu(A_p branch)
__device__ float g_pool2 [NB * 352];      // layer-2 pooled results (raw order)
__device__ float g_biasL1[288];
__device__ float g_biasP [32];
__device__ float g_biasL2[352];
__device__ float g_wsum10[32];

// Ucat segment j (cols 32j..32j+31 of raw layout, j<8) <-> layer-2 pair index
__device__ const int c_pmap[8] = {0, 4, 5, 6, 7, 8, 9, 10};
// raw offset of pooled2[pair i] inside g_pool2 row
__device__ const int c_off[11] = {0, 256, 288, 320, 32, 64, 96, 128, 160, 192, 224};

// ---------------- packed f32x2 helpers ----------------
__device__ __forceinline__ unsigned long long packdup(float x) {
    unsigned long long r;
    unsigned int xi = __float_as_uint(x);
    asm("mov.b64 %0, {%1, %2};" : "=l"(r) : "r"(xi), "r"(xi));
    return r;
}
__device__ __forceinline__ void fma2(unsigned long long &d,
                                     unsigned long long a,
                                     unsigned long long b) {
    asm("fma.rn.f32x2 %0, %1, %2, %0;" : "+l"(d) : "l"(a), "l"(b));
}
__device__ __forceinline__ float2 unpack2(unsigned long long v) {
    unsigned int lo, hi;
    asm("mov.b64 {%0, %1}, %2;" : "=r"(lo), "=r"(hi) : "l"(v));
    float2 f;
    f.x = __uint_as_float(lo);
    f.y = __uint_as_float(hi);
    return f;
}

// ---------------- init: zero accumulators, prepare bias vectors ----------------
__global__ void k_init(const float* __restrict__ b1a, const float* __restrict__ b1b,
                       const float* __restrict__ b2,  const float* __restrict__ W2) {
    int t = threadIdx.x;  // 512 threads, one block
    for (int i = t; i < NB * 352; i += 512) g_pool2[i] = 0.f;
    for (int i = t; i < NB * 32;  i += 512) g_pooled[i] = 0.f;
    for (int i = t; i < 288; i += 512)
        g_biasL1[i] = (i < 96) ? b1a[(i >> 5) * 32 + (i & 31)]
                               : b1b[((i - 96) >> 5) * 32 + (i & 31)];
    for (int i = t; i < 32; i += 512) g_biasP[i] = b1a[3 * 32 + i];
    for (int i = t; i < 352; i += 512) {
        int pair = (i < 256) ? c_pmap[i >> 5] : 1 + ((i - 256) >> 5);
        g_biasL2[i] = b2[pair * 32 + (i & 31)];
    }
    for (int i = t; i < 32; i += 512) {
        float s = 0.f;
        for (int k = 0; k < 32; k++) s += W2[(10 * 32 + k) * 32 + i];
        g_wsum10[i] = s;
    }
}

// ---------------- stage A: layer-1 right operands ----------------
__global__ void k_stage_a(const float* __restrict__ xn,
                          const float* __restrict__ sg,  const float* __restrict__ st,
                          const float* __restrict__ og1, const float* __restrict__ ot1,
                          const float* __restrict__ og2, const float* __restrict__ ot2,
                          const float* __restrict__ Wa,  const float* __restrict__ Wb) {
    int idx = blockIdx.x * blockDim.x + threadIdx.x;
    if (idx >= NB * NN * 288) return;
    int c = idx % 288;
    int bn = idx / 288;
    int h = c & 31;
    float acc = 0.f;
    if (c < 96) {
        int j = c >> 5;
        const float* xr = xn + (size_t)bn * 6;
#pragma unroll
        for (int f = 0; f < 6; f++) acc += xr[f] * Wa[(j * 6 + f) * 32 + h];
    } else {
        int i = (c - 96) >> 5;
        const float* fp;
        switch (i) {
            case 0: fp = sg;  break;
            case 1: fp = st;  break;
            case 2: fp = og1; break;
            case 3: fp = ot1; break;
            case 4: fp = og2; break;
            default: fp = ot2;
        }
        const float* xr = fp + (size_t)bn * 3;
#pragma unroll
        for (int f = 0; f < 3; f++) acc += xr[f] * Wb[(i * 3 + f) * 32 + h];
    }
    g_Ycat[idx] = acc;
}

__global__ void k_stage_p(const float* __restrict__ xp, const float* __restrict__ Wa) {
    int idx = blockIdx.x * blockDim.x + threadIdx.x;
    if (idx >= NB * NP_ * 32) return;
    int h = idx & 31;
    int bn = idx >> 5;
    const float* xr = xp + (size_t)bn * 6;
    float acc = 0.f;
#pragma unroll
    for (int f = 0; f < 6; f++) acc += xr[f] * Wa[(3 * 6 + f) * 32 + h];
    g_Yp[idx] = acc;
}

// ---------------- stage C: layer-2 right operands U = Z @ W_l2 ----------------
__global__ void k_stage_c(const float* __restrict__ W2) {
    int idx = blockIdx.x * blockDim.x + threadIdx.x;
    if (idx >= NB * NN * 352) return;
    int c = idx % 352;
    int bn = idx / 352;
    int b = bn >> 11;
    int n = bn & 2047;
    int h = c & 31;
    int pair = (c < 256) ? c_pmap[c >> 5] : 1 + ((c - 256) >> 5);
    float acc;
    if (pair == 10) {
        acc = g_pooled[b * 32 + (n >> 6)] * g_wsum10[h];
    } else {
        int zbase;
        if (pair == 0) zbase = 0;
        else if (pair <= 2) zbase = 32;        // x12
        else if (pair == 3) zbase = 64;        // x13
        else zbase = 96 + 32 * (pair - 4);     // xb[pair-4]
        const float* zr = g_Z + (size_t)bn * 288 + zbase;
        const float* wr = W2 + (pair * 32) * 32 + h;
        acc = 0.f;
#pragma unroll
        for (int k = 0; k < 32; k++) acc += zr[k] * wr[k * 32];
    }
    g_U[idx] = acc;
}

// ---------------- tiled GEMM: C = relu(A @ B + bias), opt. row-sum reduce ----------------
#define BM 128
#define BN 64
#define BK 16

template <bool REDUCE>
__device__ __forceinline__ void gemm_body(
    const float* __restrict__ gA,    // M x K, lda = K (batch-adjusted)
    const float* __restrict__ gB,    // K x *, ldb (batch- and column-base-adjusted)
    float* __restrict__ gC,          // ldc (WRITE path)
    float* __restrict__ pool,        // batch-adjusted pool row (REDUCE path)
    const float* __restrict__ bias,  // indexed by n0 + local col
    int M, int K, int Ncols, int ldb, int ldc, int n0) {
    __shared__ float As[BK][BM + 4];
    __shared__ float Bs[BK][BN];
    __shared__ float red[16][64];

    int lid = threadIdx.x;        // 256 threads
    int tx = lid & 15;            // n-direction (x4 cols)
    int ty = lid >> 4;            // m-direction (x8 rows)
    int m0 = blockIdx.y * BM;

    unsigned long long acc[4][4];
#pragma unroll
    for (int i = 0; i < 4; i++)
#pragma unroll
        for (int j = 0; j < 4; j++) acc[i][j] = 0ull;

    int arow = lid >> 2;
    int ac4 = lid & 3;
    int brow = lid >> 4;
    int bcol = (lid & 15) << 2;
    bool bvalid = (n0 + bcol) < Ncols;

    for (int k0 = 0; k0 < K; k0 += BK) {
        // A tile -> transposed into shared
#pragma unroll
        for (int r = 0; r < 2; r++) {
            int row = arow + r * 64;
            float4 v = *reinterpret_cast<const float4*>(
                gA + (size_t)(m0 + row) * K + k0 + (ac4 << 2));
            As[(ac4 << 2) + 0][row] = v.x;
            As[(ac4 << 2) + 1][row] = v.y;
            As[(ac4 << 2) + 2][row] = v.z;
            As[(ac4 << 2) + 3][row] = v.w;
        }
        float4 bv = make_float4(0.f, 0.f, 0.f, 0.f);
        if (bvalid)
            bv = *reinterpret_cast<const float4*>(
                gB + (size_t)(k0 + brow) * ldb + n0 + bcol);
        *reinterpret_cast<float4*>(&Bs[brow][bcol]) = bv;
        __syncthreads();

#pragma unroll
        for (int k = 0; k < BK; k++) {
            unsigned long long a2[4];
#pragma unroll
            for (int ii = 0; ii < 4; ii++)
                a2[ii] = *reinterpret_cast<const unsigned long long*>(
                    &As[k][ty * 8 + (ii << 1)]);
            float4 bq = *reinterpret_cast<const float4*>(&Bs[k][tx << 2]);
            unsigned long long b2[4];
            b2[0] = packdup(bq.x);
            b2[1] = packdup(bq.y);
            b2[2] = packdup(bq.z);
            b2[3] = packdup(bq.w);
#pragma unroll
            for (int ii = 0; ii < 4; ii++)
#pragma unroll
                for (int j = 0; j < 4; j++) fma2(acc[ii][j], a2[ii], b2[j]);
        }
        __syncthreads();
    }

    // epilogue
    float cv[8][4];
#pragma unroll
    for (int ii = 0; ii < 4; ii++)
#pragma unroll
        for (int j = 0; j < 4; j++) {
            float2 f = unpack2(acc[ii][j]);
            cv[2 * ii + 0][j] = f.x;
            cv[2 * ii + 1][j] = f.y;
        }
    float bb[4];
#pragma unroll
    for (int j = 0; j < 4; j++) {
        int n = n0 + (tx << 2) + j;
        bb[j] = (n < Ncols) ? bias[n] : 0.f;
    }
    if (!REDUCE) {
        if (bvalid) {
#pragma unroll
            for (int r = 0; r < 8; r++) {
                float4 o;
                o.x = fmaxf(cv[r][0] + bb[0], 0.f);
                o.y = fmaxf(cv[r][1] + bb[1], 0.f);
                o.z = fmaxf(cv[r][2] + bb[2], 0.f);
                o.w = fmaxf(cv[r][3] + bb[3], 0.f);
                *reinterpret_cast<float4*>(
                    gC + (size_t)(m0 + ty * 8 + r) * ldc + n0 + (tx << 2)) = o;
            }
        }
    } else {
        float ps[4] = {0.f, 0.f, 0.f, 0.f};
#pragma unroll
        for (int r = 0; r < 8; r++)
#pragma unroll
            for (int j = 0; j < 4; j++) ps[j] += fmaxf(cv[r][j] + bb[j], 0.f);
#pragma unroll
        for (int j = 0; j < 4; j++) red[ty][(tx << 2) + j] = ps[j];
        __syncthreads();
        if (lid < 64) {
            float s = 0.f;
#pragma unroll
            for (int t = 0; t < 16; t++) s += red[t][lid];
            if (n0 + lid < Ncols) atomicAdd(&pool[n0 + lid], s);
        }
    }
}

// layer-1 main graph: Z = relu(A_n @ Ycat + biasL1)   grid (5,16,8)
__global__ void __launch_bounds__(256) k_gemm_l1(const float* __restrict__ An) {
    int b = blockIdx.z;
    gemm_body<false>(An + (size_t)b * NN * NN,
                     g_Ycat + (size_t)b * NN * 288,
                     g_Z + (size_t)b * NN * 288,
                     nullptr, g_biasL1,
                     NN, NN, 288, 288, 288, blockIdx.x * BN);
}

// A_p branch: pooled = sum_n relu(A_p @ Yp + biasP)   grid (1,8,8)
__global__ void __launch_bounds__(256) k_gemm_p(const float* __restrict__ Ap) {
    int b = blockIdx.z;
    gemm_body<true>(Ap + (size_t)b * NP_ * NP_,
                    g_Yp + (size_t)b * NP_ * 32,
                    nullptr, g_pooled + b * 32, g_biasP,
                    NP_, NP_, 32, 32, 0, 0);
}

// layer-2 (all 11 pairs): pool2 += sum_n relu(A @ U + biasL2)   grid (7,16,8)
__global__ void __launch_bounds__(256) k_gemm_l2(const float* __restrict__ An,
                                                 const float* __restrict__ Ats,
                                                 const float* __restrict__ Acs,
                                                 const float* __restrict__ Asl) {
    int b = blockIdx.z;
    int slot = blockIdx.x;
    const float* A;
    int n0, bofs, ncols;
    if (slot < 4) {
        A = An; n0 = slot * BN; bofs = 0; ncols = 256;
    } else {
        A = (slot == 4) ? Ats : ((slot == 5) ? Acs : Asl);
        n0 = 0; bofs = 256 + 32 * (slot - 4); ncols = 32;
    }
    gemm_body<true>(A + (size_t)b * NN * NN,
                    g_U + (size_t)b * NN * 352 + bofs,
                    nullptr, g_pool2 + b * 352 + bofs, g_biasL2 + bofs,
                    NN, NN, ncols, 352, 0, n0);
}

// ---------------- dense head ----------------
__global__ void k_dense(const float* __restrict__ Wd1, const float* __restrict__ bd1,
                        const float* __restrict__ Wd2, const float* __restrict__ bd2,
                        const float* __restrict__ Wo,  const float* __restrict__ bo,
                        float* __restrict__ out) {
    __shared__ float sq[352];
    __shared__ float h1[128];
    __shared__ float h2[128];
    __shared__ float rbuf[128];
    int t = threadIdx.x;  // 128 threads
    for (int b = 0; b < NB; b++) {
        for (int i = t; i < 352; i += 128) {
            int p = i >> 5;
            sq[i] = g_pool2[b * 352 + c_off[p] + (i & 31)];
        }
        __syncthreads();
        float acc = bd1[t];
        for (int k = 0; k < 352; k++) acc += sq[k] * Wd1[k * 128 + t];
        h1[t] = fmaxf(acc, 0.f);
        __syncthreads();
        float a2 = bd2[t];
        for (int k = 0; k < 128; k++) a2 += h1[k] * Wd2[k * 128 + t];
        h2[t] = fmaxf(a2, 0.f);
        __syncthreads();
        rbuf[t] = h2[t] * Wo[t];
        __syncthreads();
        for (int w = 64; w > 0; w >>= 1) {
            if (t < w) rbuf[t] += rbuf[t + w];
            __syncthreads();
        }
        if (t == 0) out[b] = rbuf[0] + bo[0];
        __syncthreads();
    }
}

// ---------------- launch ----------------
extern "C" void kernel_launch(void* const* d_in, const int* in_sizes, int n_in,
                              void* d_out, int out_size) {
    const float* x_n     = (const float*)d_in[0];
    const float* A_n     = (const float*)d_in[1];
    const float* A_s     = (const float*)d_in[2];
    const float* A_n_ts  = (const float*)d_in[3];
    const float* A_n_cs  = (const float*)d_in[4];
    // d_in[5] mask — unused by the model
    const float* x_p     = (const float*)d_in[6];
    const float* A_p     = (const float*)d_in[7];
    const float* self_g  = (const float*)d_in[8];
    const float* self_t  = (const float*)d_in[9];
    const float* other_g1 = (const float*)d_in[10];
    const float* other_t1 = (const float*)d_in[11];
    const float* other_g2 = (const float*)d_in[12];
    const float* other_t2 = (const float*)d_in[13];
    const float* W_l1a   = (const float*)d_in[14];
    const float* b_l1a   = (const float*)d_in[15];
    const float* W_l1b   = (const float*)d_in[16];
    const float* b_l1b   = (const float*)d_in[17];
    const float* W_l2    = (const float*)d_in[18];
    const float* b_l2    = (const float*)d_in[19];
    const float* Wd1     = (const float*)d_in[20];
    const float* bd1     = (const float*)d_in[21];
    const float* Wd2     = (const float*)d_in[22];
    const float* bd2     = (const float*)d_in[23];
    const float* Wo      = (const float*)d_in[24];
    const float* bo      = (const float*)d_in[25];
    float* out = (float*)d_out;

    k_init<<<1, 512>>>(b_l1a, b_l1b, b_l2, W_l2);

    {
        int tot = NB * NN * 288;
        k_stage_a<<<(tot + 255) / 256, 256>>>(x_n, self_g, self_t, other_g1,
                                              other_t1, other_g2, other_t2,
                                              W_l1a, W_l1b);
    }
    {
        int tot = NB * NP_ * 32;
        k_stage_p<<<(tot + 255) / 256, 256>>>(x_p, W_l1a);
    }

    k_gemm_l1<<<dim3(5, 16, NB), 256>>>(A_n);
    k_gemm_p<<<dim3(1, 8, NB), 256>>>(A_p);

    {
        int tot = NB * NN * 352;
        k_stage_c<<<(tot + 255) / 256, 256>>>(W_l2);
    }

    k_gemm_l2<<<dim3(7, 16, NB), 256>>>(A_n, A_n_ts, A_n_cs, A_s);

    k_dense<<<1, 128>>>(Wd1, bd1, Wd2, bd2, Wo, bo, out);
}

// round 11
// speedup vs baseline: 1.0017x; 1.0017x over previous
#include <cuda_runtime.h>
#include <cuda_bf16.h>

// Problem constants
// B=8, N=2048, NP=1024, FN=6, FS=3, H=32, NQ=128
#define NB   8
#define NN   2048
#define NP_  1024
#define H_   32

// ---------------- scratch (device globals; no allocation) ----------------
__device__ float g_Ycat[NB * NN * 288];   // layer-1 right operands (9 x 32 cols)
__device__ float g_Z   [NB * NN * 288];   // layer-1 relu outputs x11,x12,x13,xb0..xb5
__device__ float g_Yp  [NB * NP_ * 32];   // x_p @ W_l1a[3]
__device__ float g_U   [NB * NN * 352];   // layer-2 right operands (raw order)
__device__ float g_pooled[NB * 32];       // sum over nodes of relu(A_p branch)
__device__ float g_pool2 [NB * 352];      // layer-2 pooled results (raw order)
__device__ float g_biasL1[288];
__device__ float g_biasP [32];
__device__ float g_biasL2[352];
__device__ float g_wsum10[32];

// Ucat segment j (cols 32j..32j+31 of raw layout, j<8) <-> layer-2 pair index
__device__ const int c_pmap[8] = {0, 4, 5, 6, 7, 8, 9, 10};
// raw offset of pooled2[pair i] inside g_pool2 row
__device__ const int c_off[11] = {0, 256, 288, 320, 32, 64, 96, 128, 160, 192, 224};

// ---------------- packed f32x2 helpers ----------------
__device__ __forceinline__ unsigned long long packdup(float x) {
    unsigned long long r;
    unsigned int xi = __float_as_uint(x);
    asm("mov.b64 %0, {%1, %2};" : "=l"(r) : "r"(xi), "r"(xi));
    return r;
}
__device__ __forceinline__ void fma2(unsigned long long &d,
                                     unsigned long long a,
                                     unsigned long long b) {
    asm("fma.rn.f32x2 %0, %1, %2, %0;" : "+l"(d) : "l"(a), "l"(b));
}
__device__ __forceinline__ float2 unpack2(unsigned long long v) {
    unsigned int lo, hi;
    asm("mov.b64 {%0, %1}, %2;" : "=r"(lo), "=r"(hi) : "l"(v));
    float2 f;
    f.x = __uint_as_float(lo);
    f.y = __uint_as_float(hi);
    return f;
}

// ---------------- init: zero accumulators, prepare bias vectors ----------------
__global__ void k_init(const float* __restrict__ b1a, const float* __restrict__ b1b,
                       const float* __restrict__ b2,  const float* __restrict__ W2) {
    int t = threadIdx.x;  // 512 threads, one block
    for (int i = t; i < NB * 352; i += 512) g_pool2[i] = 0.f;
    for (int i = t; i < NB * 32;  i += 512) g_pooled[i] = 0.f;
    for (int i = t; i < 288; i += 512)
        g_biasL1[i] = (i < 96) ? b1a[(i >> 5) * 32 + (i & 31)]
                               : b1b[((i - 96) >> 5) * 32 + (i & 31)];
    for (int i = t; i < 32; i += 512) g_biasP[i] = b1a[3 * 32 + i];
    for (int i = t; i < 352; i += 512) {
        int pair = (i < 256) ? c_pmap[i >> 5] : 1 + ((i - 256) >> 5);
        g_biasL2[i] = b2[pair * 32 + (i & 31)];
    }
    for (int i = t; i < 32; i += 512) {
        float s = 0.f;
        for (int k = 0; k < 32; k++) s += W2[(10 * 32 + k) * 32 + i];
        g_wsum10[i] = s;
    }
}

// ---------------- stage A: layer-1 right operands ----------------
__global__ void k_stage_a(const float* __restrict__ xn,
                          const float* __restrict__ sg,  const float* __restrict__ st,
                          const float* __restrict__ og1, const float* __restrict__ ot1,
                          const float* __restrict__ og2, const float* __restrict__ ot2,
                          const float* __restrict__ Wa,  const float* __restrict__ Wb) {
    int idx = blockIdx.x * blockDim.x + threadIdx.x;
    if (idx >= NB * NN * 288) return;
    int c = idx % 288;
    int bn = idx / 288;
    int h = c & 31;
    float acc = 0.f;
    if (c < 96) {
        int j = c >> 5;
        const float* xr = xn + (size_t)bn * 6;
#pragma unroll
        for (int f = 0; f < 6; f++) acc += xr[f] * Wa[(j * 6 + f) * 32 + h];
    } else {
        int i = (c - 96) >> 5;
        const float* fp;
        switch (i) {
            case 0: fp = sg;  break;
            case 1: fp = st;  break;
            case 2: fp = og1; break;
            case 3: fp = ot1; break;
            case 4: fp = og2; break;
            default: fp = ot2;
        }
        const float* xr = fp + (size_t)bn * 3;
#pragma unroll
        for (int f = 0; f < 3; f++) acc += xr[f] * Wb[(i * 3 + f) * 32 + h];
    }
    g_Ycat[idx] = acc;
}

__global__ void k_stage_p(const float* __restrict__ xp, const float* __restrict__ Wa) {
    int idx = blockIdx.x * blockDim.x + threadIdx.x;
    if (idx >= NB * NP_ * 32) return;
    int h = idx & 31;
    int bn = idx >> 5;
    const float* xr = xp + (size_t)bn * 6;
    float acc = 0.f;
#pragma unroll
    for (int f = 0; f < 6; f++) acc += xr[f] * Wa[(3 * 6 + f) * 32 + h];
    g_Yp[idx] = acc;
}

// ---------------- stage C: layer-2 right operands U = Z @ W_l2 ----------------
__global__ void k_stage_c(const float* __restrict__ W2) {
    int idx = blockIdx.x * blockDim.x + threadIdx.x;
    if (idx >= NB * NN * 352) return;
    int c = idx % 352;
    int bn = idx / 352;
    int b = bn >> 11;
    int n = bn & 2047;
    int h = c & 31;
    int pair = (c < 256) ? c_pmap[c >> 5] : 1 + ((c - 256) >> 5);
    float acc;
    if (pair == 10) {
        acc = g_pooled[b * 32 + (n >> 6)] * g_wsum10[h];
    } else {
        int zbase;
        if (pair == 0) zbase = 0;
        else if (pair <= 2) zbase = 32;        // x12
        else if (pair == 3) zbase = 64;        // x13
        else zbase = 96 + 32 * (pair - 4);     // xb[pair-4]
        const float* zr = g_Z + (size_t)bn * 288 + zbase;
        const float* wr = W2 + (pair * 32) * 32 + h;
        acc = 0.f;
#pragma unroll
        for (int k = 0; k < 32; k++) acc += zr[k] * wr[k * 32];
    }
    g_U[idx] = acc;
}

// ---------------- tiled GEMM: C = relu(A @ B + bias), opt. row-sum reduce ----------------
#define BM 128
#define BN 64
#define BK 16

template <bool REDUCE>
__device__ __forceinline__ void gemm_body(
    const float* __restrict__ gA,    // M x K, lda = K (batch-adjusted)
    const float* __restrict__ gB,    // K x *, ldb (batch- and column-base-adjusted)
    float* __restrict__ gC,          // ldc (WRITE path)
    float* __restrict__ pool,        // batch-adjusted pool row (REDUCE path)
    const float* __restrict__ bias,  // indexed by n0 + local col
    int M, int K, int Ncols, int ldb, int ldc, int n0) {
    __shared__ float As[BK][BM + 4];
    __shared__ float Bs[BK][BN];
    __shared__ float red[16][64];

    int lid = threadIdx.x;        // 256 threads
    int tx = lid & 15;            // n-direction (x4 cols)
    int ty = lid >> 4;            // m-direction (x8 rows)
    int m0 = blockIdx.y * BM;

    unsigned long long acc[4][4];
#pragma unroll
    for (int i = 0; i < 4; i++)
#pragma unroll
        for (int j = 0; j < 4; j++) acc[i][j] = 0ull;

    int arow = lid >> 2;
    int ac4 = lid & 3;
    int brow = lid >> 4;
    int bcol = (lid & 15) << 2;
    bool bvalid = (n0 + bcol) < Ncols;

    for (int k0 = 0; k0 < K; k0 += BK) {
        // A tile -> transposed into shared
#pragma unroll
        for (int r = 0; r < 2; r++) {
            int row = arow + r * 64;
            float4 v = *reinterpret_cast<const float4*>(
                gA + (size_t)(m0 + row) * K + k0 + (ac4 << 2));
            As[(ac4 << 2) + 0][row] = v.x;
            As[(ac4 << 2) + 1][row] = v.y;
            As[(ac4 << 2) + 2][row] = v.z;
            As[(ac4 << 2) + 3][row] = v.w;
        }
        float4 bv = make_float4(0.f, 0.f, 0.f, 0.f);
        if (bvalid)
            bv = *reinterpret_cast<const float4*>(
                gB + (size_t)(k0 + brow) * ldb + n0 + bcol);
        *reinterpret_cast<float4*>(&Bs[brow][bcol]) = bv;
        __syncthreads();

#pragma unroll
        for (int k = 0; k < BK; k++) {
            unsigned long long a2[4];
#pragma unroll
            for (int ii = 0; ii < 4; ii++)
                a2[ii] = *reinterpret_cast<const unsigned long long*>(
                    &As[k][ty * 8 + (ii << 1)]);
            float4 bq = *reinterpret_cast<const float4*>(&Bs[k][tx << 2]);
            unsigned long long b2[4];
            b2[0] = packdup(bq.x);
            b2[1] = packdup(bq.y);
            b2[2] = packdup(bq.z);
            b2[3] = packdup(bq.w);
#pragma unroll
            for (int ii = 0; ii < 4; ii++)
#pragma unroll
                for (int j = 0; j < 4; j++) fma2(acc[ii][j], a2[ii], b2[j]);
        }
        __syncthreads();
    }

    // epilogue
    float cv[8][4];
#pragma unroll
    for (int ii = 0; ii < 4; ii++)
#pragma unroll
        for (int j = 0; j < 4; j++) {
            float2 f = unpack2(acc[ii][j]);
            cv[2 * ii + 0][j] = f.x;
            cv[2 * ii + 1][j] = f.y;
        }
    float bb[4];
#pragma unroll
    for (int j = 0; j < 4; j++) {
        int n = n0 + (tx << 2) + j;
        bb[j] = (n < Ncols) ? bias[n] : 0.f;
    }
    if (!REDUCE) {
        if (bvalid) {
#pragma unroll
            for (int r = 0; r < 8; r++) {
                float4 o;
                o.x = fmaxf(cv[r][0] + bb[0], 0.f);
                o.y = fmaxf(cv[r][1] + bb[1], 0.f);
                o.z = fmaxf(cv[r][2] + bb[2], 0.f);
                o.w = fmaxf(cv[r][3] + bb[3], 0.f);
                *reinterpret_cast<float4*>(
                    gC + (size_t)(m0 + ty * 8 + r) * ldc + n0 + (tx << 2)) = o;
            }
        }
    } else {
        float ps[4] = {0.f, 0.f, 0.f, 0.f};
#pragma unroll
        for (int r = 0; r < 8; r++)
#pragma unroll
            for (int j = 0; j < 4; j++) ps[j] += fmaxf(cv[r][j] + bb[j], 0.f);
#pragma unroll
        for (int j = 0; j < 4; j++) red[ty][(tx << 2) + j] = ps[j];
        __syncthreads();
        if (lid < 64) {
            float s = 0.f;
#pragma unroll
            for (int t = 0; t < 16; t++) s += red[t][lid];
            if (n0 + lid < Ncols) atomicAdd(&pool[n0 + lid], s);
        }
    }
}

// layer-1 main graph: Z = relu(A_n @ Ycat + biasL1)   grid (5,16,8)
__global__ void __launch_bounds__(256) k_gemm_l1(const float* __restrict__ An) {
    int b = blockIdx.z;
    gemm_body<false>(An + (size_t)b * NN * NN,
                     g_Ycat + (size_t)b * NN * 288,
                     g_Z + (size_t)b * NN * 288,
                     nullptr, g_biasL1,
                     NN, NN, 288, 288, 288, blockIdx.x * BN);
}

// A_p branch: pooled = sum_n relu(A_p @ Yp + biasP)   grid (1,8,8)
__global__ void __launch_bounds__(256) k_gemm_p(const float* __restrict__ Ap) {
    int b = blockIdx.z;
    gemm_body<true>(Ap + (size_t)b * NP_ * NP_,
                    g_Yp + (size_t)b * NP_ * 32,
                    nullptr, g_pooled + b * 32, g_biasP,
                    NP_, NP_, 32, 32, 0, 0);
}

// layer-2 (all 11 pairs): pool2 += sum_n relu(A @ U + biasL2)   grid (7,16,8)
__global__ void __launch_bounds__(256) k_gemm_l2(const float* __restrict__ An,
                                                 const float* __restrict__ Ats,
                                                 const float* __restrict__ Acs,
                                                 const float* __restrict__ Asl) {
    int b = blockIdx.z;
    int slot = blockIdx.x;
    const float* A;
    int n0, bofs, ncols;
    if (slot < 4) {
        A = An; n0 = slot * BN; bofs = 0; ncols = 256;
    } else {
        A = (slot == 4) ? Ats : ((slot == 5) ? Acs : Asl);
        n0 = 0; bofs = 256 + 32 * (slot - 4); ncols = 32;
    }
    gemm_body<true>(A + (size_t)b * NN * NN,
                    g_U + (size_t)b * NN * 352 + bofs,
                    nullptr, g_pool2 + b * 352 + bofs, g_biasL2 + bofs,
                    NN, NN, ncols, 352, 0, n0);
}

// ---------------- dense head ----------------
__global__ void k_dense(const float* __restrict__ Wd1, const float* __restrict__ bd1,
                        const float* __restrict__ Wd2, const float* __restrict__ bd2,
                        const float* __restrict__ Wo,  const float* __restrict__ bo,
                        float* __restrict__ out) {
    __shared__ float sq[352];
    __shared__ float h1[128];
    __shared__ float h2[128];
    __shared__ float rbuf[128];
    int t = threadIdx.x;  // 128 threads
    for (int b = 0; b < NB; b++) {
        for (int i = t; i < 352; i += 128) {
            int p = i >> 5;
            sq[i] = g_pool2[b * 352 + c_off[p] + (i & 31)];
        }
        __syncthreads();
        float acc = bd1[t];
        for (int k = 0; k < 352; k++) acc += sq[k] * Wd1[k * 128 + t];
        h1[t] = fmaxf(acc, 0.f);
        __syncthreads();
        float a2 = bd2[t];
        for (int k = 0; k < 128; k++) a2 += h1[k] * Wd2[k * 128 + t];
        h2[t] = fmaxf(a2, 0.f);
        __syncthreads();
        rbuf[t] = h2[t] * Wo[t];
        __syncthreads();
        for (int w = 64; w > 0; w >>= 1) {
            if (t < w) rbuf[t] += rbuf[t + w];
            __syncthreads();
        }
        if (t == 0) out[b] = rbuf[0] + bo[0];
        __syncthreads();
    }
}

// ---------------- launch ----------------
extern "C" void kernel_launch(void* const* d_in, const int* in_sizes, int n_in,
                              void* d_out, int out_size) {
    const float* x_n     = (const float*)d_in[0];
    const float* A_n     = (const float*)d_in[1];
    const float* A_s     = (const float*)d_in[2];
    const float* A_n_ts  = (const float*)d_in[3];
    const float* A_n_cs  = (const float*)d_in[4];
    // d_in[5] mask — unused by the model
    const float* x_p     = (const float*)d_in[6];
    const float* A_p     = (const float*)d_in[7];
    const float* self_g  = (const float*)d_in[8];
    const float* self_t  = (const float*)d_in[9];
    const float* other_g1 = (const float*)d_in[10];
    const float* other_t1 = (const float*)d_in[11];
    const float* other_g2 = (const float*)d_in[12];
    const float* other_t2 = (const float*)d_in[13];
    const float* W_l1a   = (const float*)d_in[14];
    const float* b_l1a   = (const float*)d_in[15];
    const float* W_l1b   = (const float*)d_in[16];
    const float* b_l1b   = (const float*)d_in[17];
    const float* W_l2    = (const float*)d_in[18];
    const float* b_l2    = (const float*)d_in[19];
    const float* Wd1     = (const float*)d_in[20];
    const float* bd1     = (const float*)d_in[21];
    const float* Wd2     = (const float*)d_in[22];
    const float* bd2     = (const float*)d_in[23];
    const float* Wo      = (const float*)d_in[24];
    const float* bo      = (const float*)d_in[25];
    float* out = (float*)d_out;

    k_init<<<1, 512>>>(b_l1a, b_l1b, b_l2, W_l2);

    {
        int tot = NB * NN * 288;
        k_stage_a<<<(tot + 255) / 256, 256>>>(x_n, self_g, self_t, other_g1,
                                              other_t1, other_g2, other_t2,
                                              W_l1a, W_l1b);
    }
    {
        int tot = NB * NP_ * 32;
        k_stage_p<<<(tot + 255) / 256, 256>>>(x_p, W_l1a);
    }

    k_gemm_l1<<<dim3(5, 16, NB), 256>>>(A_n);
    k_gemm_p<<<dim3(1, 8, NB), 256>>>(A_p);

    {
        int tot = NB * NN * 352;
        k_stage_c<<<(tot + 255) / 256, 256>>>(W_l2);
    }

    k_gemm_l2<<<dim3(7, 16, NB), 256>>>(A_n, A_n_ts, A_n_cs, A_s);

    k_dense<<<1, 128>>>(Wd1, bd1, Wd2, bd2, Wo, bo, out);
}

// round 12
// speedup vs baseline: 1.0023x; 1.0006x over previous
#include <cuda_runtime.h>
#include <cuda_bf16.h>

// Problem constants
// B=8, N=2048, NP=1024, FN=6, FS=3, H=32, NQ=128
#define NB   8
#define NN   2048
#define NP_  1024
#define H_   32

// ---------------- scratch (device globals; no allocation) ----------------
__device__ float g_Ycat[NB * NN * 288];   // layer-1 right operands (9 x 32 cols)
__device__ float g_Z   [NB * NN * 288];   // layer-1 relu outputs x11,x12,x13,xb0..xb5
__device__ float g_Yp  [NB * NP_ * 32];   // x_p @ W_l1a[3]
__device__ float g_U   [NB * NN * 352];   // layer-2 right operands (raw order)
__device__ float g_pooled[NB * 32];       // sum over nodes of relu(A_p branch)
__device__ float g_pool2 [NB * 352];      // layer-2 pooled results (raw order)
__device__ float g_biasL1[288];
__device__ float g_biasP [32];
__device__ float g_biasL2[352];
__device__ float g_wsum10[32];

// Ucat segment j (cols 32j..32j+31 of raw layout, j<8) <-> layer-2 pair index
__device__ const int c_pmap[8] = {0, 4, 5, 6, 7, 8, 9, 10};
// raw offset of pooled2[pair i] inside g_pool2 row
__device__ const int c_off[11] = {0, 256, 288, 320, 32, 64, 96, 128, 160, 192, 224};

// ---------------- packed f32x2 helpers ----------------
__device__ __forceinline__ unsigned long long packdup(float x) {
    unsigned long long r;
    unsigned int xi = __float_as_uint(x);
    asm("mov.b64 %0, {%1, %2};" : "=l"(r) : "r"(xi), "r"(xi));
    return r;
}
__device__ __forceinline__ void fma2(unsigned long long &d,
                                     unsigned long long a,
                                     unsigned long long b) {
    asm("fma.rn.f32x2 %0, %1, %2, %0;" : "+l"(d) : "l"(a), "l"(b));
}
__device__ __forceinline__ float2 unpack2(unsigned long long v) {
    unsigned int lo, hi;
    asm("mov.b64 {%0, %1}, %2;" : "=r"(lo), "=r"(hi) : "l"(v));
    float2 f;
    f.x = __uint_as_float(lo);
    f.y = __uint_as_float(hi);
    return f;
}

// ---------------- init: zero accumulators, prepare bias vectors ----------------
__global__ void k_init(const float* __restrict__ b1a, const float* __restrict__ b1b,
                       const float* __restrict__ b2,  const float* __restrict__ W2) {
    int t = threadIdx.x;  // 512 threads, one block
    for (int i = t; i < NB * 352; i += 512) g_pool2[i] = 0.f;
    for (int i = t; i < NB * 32;  i += 512) g_pooled[i] = 0.f;
    for (int i = t; i < 288; i += 512)
        g_biasL1[i] = (i < 96) ? b1a[(i >> 5) * 32 + (i & 31)]
                               : b1b[((i - 96) >> 5) * 32 + (i & 31)];
    for (int i = t; i < 32; i += 512) g_biasP[i] = b1a[3 * 32 + i];
    for (int i = t; i < 352; i += 512) {
        int pair = (i < 256) ? c_pmap[i >> 5] : 1 + ((i - 256) >> 5);
        g_biasL2[i] = b2[pair * 32 + (i & 31)];
    }
    for (int i = t; i < 32; i += 512) {
        float s = 0.f;
        for (int k = 0; k < 32; k++) s += W2[(10 * 32 + k) * 32 + i];
        g_wsum10[i] = s;
    }
}

// ---------------- stage A: layer-1 right operands ----------------
__global__ void k_stage_a(const float* __restrict__ xn,
                          const float* __restrict__ sg,  const float* __restrict__ st,
                          const float* __restrict__ og1, const float* __restrict__ ot1,
                          const float* __restrict__ og2, const float* __restrict__ ot2,
                          const float* __restrict__ Wa,  const float* __restrict__ Wb) {
    int idx = blockIdx.x * blockDim.x + threadIdx.x;
    if (idx >= NB * NN * 288) return;
    int c = idx % 288;
    int bn = idx / 288;
    int h = c & 31;
    float acc = 0.f;
    if (c < 96) {
        int j = c >> 5;
        const float* xr = xn + (size_t)bn * 6;
#pragma unroll
        for (int f = 0; f < 6; f++) acc += xr[f] * Wa[(j * 6 + f) * 32 + h];
    } else {
        int i = (c - 96) >> 5;
        const float* fp;
        switch (i) {
            case 0: fp = sg;  break;
            case 1: fp = st;  break;
            case 2: fp = og1; break;
            case 3: fp = ot1; break;
            case 4: fp = og2; break;
            default: fp = ot2;
        }
        const float* xr = fp + (size_t)bn * 3;
#pragma unroll
        for (int f = 0; f < 3; f++) acc += xr[f] * Wb[(i * 3 + f) * 32 + h];
    }
    g_Ycat[idx] = acc;
}

__global__ void k_stage_p(const float* __restrict__ xp, const float* __restrict__ Wa) {
    int idx = blockIdx.x * blockDim.x + threadIdx.x;
    if (idx >= NB * NP_ * 32) return;
    int h = idx & 31;
    int bn = idx >> 5;
    const float* xr = xp + (size_t)bn * 6;
    float acc = 0.f;
#pragma unroll
    for (int f = 0; f < 6; f++) acc += xr[f] * Wa[(3 * 6 + f) * 32 + h];
    g_Yp[idx] = acc;
}

// ---------------- stage C: layer-2 right operands U = Z @ W_l2 ----------------
__global__ void k_stage_c(const float* __restrict__ W2) {
    int idx = blockIdx.x * blockDim.x + threadIdx.x;
    if (idx >= NB * NN * 352) return;
    int c = idx % 352;
    int bn = idx / 352;
    int b = bn >> 11;
    int n = bn & 2047;
    int h = c & 31;
    int pair = (c < 256) ? c_pmap[c >> 5] : 1 + ((c - 256) >> 5);
    float acc;
    if (pair == 10) {
        acc = g_pooled[b * 32 + (n >> 6)] * g_wsum10[h];
    } else {
        int zbase;
        if (pair == 0) zbase = 0;
        else if (pair <= 2) zbase = 32;        // x12
        else if (pair == 3) zbase = 64;        // x13
        else zbase = 96 + 32 * (pair - 4);     // xb[pair-4]
        const float* zr = g_Z + (size_t)bn * 288 + zbase;
        const float* wr = W2 + (pair * 32) * 32 + h;
        acc = 0.f;
#pragma unroll
        for (int k = 0; k < 32; k++) acc += zr[k] * wr[k * 32];
    }
    g_U[idx] = acc;
}

// ---------------- tiled GEMM: C = relu(A @ B + bias), opt. row-sum reduce ----------------
#define BM 128
#define BN 64
#define BK 16

template <bool REDUCE>
__device__ __forceinline__ void gemm_body(
    const float* __restrict__ gA,    // M x K, lda = K (batch-adjusted)
    const float* __restrict__ gB,    // K x *, ldb (batch- and column-base-adjusted)
    float* __restrict__ gC,          // ldc (WRITE path)
    float* __restrict__ pool,        // batch-adjusted pool row (REDUCE path)
    const float* __restrict__ bias,  // indexed by n0 + local col
    int M, int K, int Ncols, int ldb, int ldc, int n0) {
    __shared__ float As[BK][BM + 4];
    __shared__ float Bs[BK][BN];
    __shared__ float red[16][64];

    int lid = threadIdx.x;        // 256 threads
    int tx = lid & 15;            // n-direction (x4 cols)
    int ty = lid >> 4;            // m-direction (x8 rows)
    int m0 = blockIdx.y * BM;

    unsigned long long acc[4][4];
#pragma unroll
    for (int i = 0; i < 4; i++)
#pragma unroll
        for (int j = 0; j < 4; j++) acc[i][j] = 0ull;

    int arow = lid >> 2;
    int ac4 = lid & 3;
    int brow = lid >> 4;
    int bcol = (lid & 15) << 2;
    bool bvalid = (n0 + bcol) < Ncols;

    for (int k0 = 0; k0 < K; k0 += BK) {
        // A tile -> transposed into shared
#pragma unroll
        for (int r = 0; r < 2; r++) {
            int row = arow + r * 64;
            float4 v = *reinterpret_cast<const float4*>(
                gA + (size_t)(m0 + row) * K + k0 + (ac4 << 2));
            As[(ac4 << 2) + 0][row] = v.x;
            As[(ac4 << 2) + 1][row] = v.y;
            As[(ac4 << 2) + 2][row] = v.z;
            As[(ac4 << 2) + 3][row] = v.w;
        }
        float4 bv = make_float4(0.f, 0.f, 0.f, 0.f);
        if (bvalid)
            bv = *reinterpret_cast<const float4*>(
                gB + (size_t)(k0 + brow) * ldb + n0 + bcol);
        *reinterpret_cast<float4*>(&Bs[brow][bcol]) = bv;
        __syncthreads();

#pragma unroll
        for (int k = 0; k < BK; k++) {
            unsigned long long a2[4];
#pragma unroll
            for (int ii = 0; ii < 4; ii++)
                a2[ii] = *reinterpret_cast<const unsigned long long*>(
                    &As[k][ty * 8 + (ii << 1)]);
            float4 bq = *reinterpret_cast<const float4*>(&Bs[k][tx << 2]);
            unsigned long long b2[4];
            b2[0] = packdup(bq.x);
            b2[1] = packdup(bq.y);
            b2[2] = packdup(bq.z);
            b2[3] = packdup(bq.w);
#pragma unroll
            for (int ii = 0; ii < 4; ii++)
#pragma unroll
                for (int j = 0; j < 4; j++) fma2(acc[ii][j], a2[ii], b2[j]);
        }
        __syncthreads();
    }

    // epilogue
    float cv[8][4];
#pragma unroll
    for (int ii = 0; ii < 4; ii++)
#pragma unroll
        for (int j = 0; j < 4; j++) {
            float2 f = unpack2(acc[ii][j]);
            cv[2 * ii + 0][j] = f.x;
            cv[2 * ii + 1][j] = f.y;
        }
    float bb[4];
#pragma unroll
    for (int j = 0; j < 4; j++) {
        int n = n0 + (tx << 2) + j;
        bb[j] = (n < Ncols) ? bias[n] : 0.f;
    }
    if (!REDUCE) {
        if (bvalid) {
#pragma unroll
            for (int r = 0; r < 8; r++) {
                float4 o;
                o.x = fmaxf(cv[r][0] + bb[0], 0.f);
                o.y = fmaxf(cv[r][1] + bb[1], 0.f);
                o.z = fmaxf(cv[r][2] + bb[2], 0.f);
                o.w = fmaxf(cv[r][3] + bb[3], 0.f);
                *reinterpret_cast<float4*>(
                    gC + (size_t)(m0 + ty * 8 + r) * ldc + n0 + (tx << 2)) = o;
            }
        }
    } else {
        float ps[4] = {0.f, 0.f, 0.f, 0.f};
#pragma unroll
        for (int r = 0; r < 8; r++)
#pragma unroll
            for (int j = 0; j < 4; j++) ps[j] += fmaxf(cv[r][j] + bb[j], 0.f);
#pragma unroll
        for (int j = 0; j < 4; j++) red[ty][(tx << 2) + j] = ps[j];
        __syncthreads();
        if (lid < 64) {
            float s = 0.f;
#pragma unroll
            for (int t = 0; t < 16; t++) s += red[t][lid];
            if (n0 + lid < Ncols) atomicAdd(&pool[n0 + lid], s);
        }
    }
}

// layer-1 main graph: Z = relu(A_n @ Ycat + biasL1)   grid (5,16,8)
__global__ void __launch_bounds__(256) k_gemm_l1(const float* __restrict__ An) {
    int b = blockIdx.z;
    gemm_body<false>(An + (size_t)b * NN * NN,
                     g_Ycat + (size_t)b * NN * 288,
                     g_Z + (size_t)b * NN * 288,
                     nullptr, g_biasL1,
                     NN, NN, 288, 288, 288, blockIdx.x * BN);
}

// A_p branch: pooled = sum_n relu(A_p @ Yp + biasP)   grid (1,8,8)
__global__ void __launch_bounds__(256) k_gemm_p(const float* __restrict__ Ap) {
    int b = blockIdx.z;
    gemm_body<true>(Ap + (size_t)b * NP_ * NP_,
                    g_Yp + (size_t)b * NP_ * 32,
                    nullptr, g_pooled + b * 32, g_biasP,
                    NP_, NP_, 32, 32, 0, 0);
}

// layer-2 (all 11 pairs): pool2 += sum_n relu(A @ U + biasL2)   grid (7,16,8)
__global__ void __launch_bounds__(256) k_gemm_l2(const float* __restrict__ An,
                                                 const float* __restrict__ Ats,
                                                 const float* __restrict__ Acs,
                                                 const float* __restrict__ Asl) {
    int b = blockIdx.z;
    int slot = blockIdx.x;
    const float* A;
    int n0, bofs, ncols;
    if (slot < 4) {
        A = An; n0 = slot * BN; bofs = 0; ncols = 256;
    } else {
        A = (slot == 4) ? Ats : ((slot == 5) ? Acs : Asl);
        n0 = 0; bofs = 256 + 32 * (slot - 4); ncols = 32;
    }
    gemm_body<true>(A + (size_t)b * NN * NN,
                    g_U + (size_t)b * NN * 352 + bofs,
                    nullptr, g_pool2 + b * 352 + bofs, g_biasL2 + bofs,
                    NN, NN, ncols, 352, 0, n0);
}

// ---------------- dense head ----------------
__global__ void k_dense(const float* __restrict__ Wd1, const float* __restrict__ bd1,
                        const float* __restrict__ Wd2, const float* __restrict__ bd2,
                        const float* __restrict__ Wo,  const float* __restrict__ bo,
                        float* __restrict__ out) {
    __shared__ float sq[352];
    __shared__ float h1[128];
    __shared__ float h2[128];
    __shared__ float rbuf[128];
    int t = threadIdx.x;  // 128 threads
    for (int b = 0; b < NB; b++) {
        for (int i = t; i < 352; i += 128) {
            int p = i >> 5;
            sq[i] = g_pool2[b * 352 + c_off[p] + (i & 31)];
        }
        __syncthreads();
        float acc = bd1[t];
        for (int k = 0; k < 352; k++) acc += sq[k] * Wd1[k * 128 + t];
        h1[t] = fmaxf(acc, 0.f);
        __syncthreads();
        float a2 = bd2[t];
        for (int k = 0; k < 128; k++) a2 += h1[k] * Wd2[k * 128 + t];
        h2[t] = fmaxf(a2, 0.f);
        __syncthreads();
        rbuf[t] = h2[t] * Wo[t];
        __syncthreads();
        for (int w = 64; w > 0; w >>= 1) {
            if (t < w) rbuf[t] += rbuf[t + w];
            __syncthreads();
        }
        if (t == 0) out[b] = rbuf[0] + bo[0];
        __syncthreads();
    }
}

// ---------------- launch ----------------
extern "C" void kernel_launch(void* const* d_in, const int* in_sizes, int n_in,
                              void* d_out, int out_size) {
    const float* x_n     = (const float*)d_in[0];
    const float* A_n     = (const float*)d_in[1];
    const float* A_s     = (const float*)d_in[2];
    const float* A_n_ts  = (const float*)d_in[3];
    const float* A_n_cs  = (const float*)d_in[4];
    // d_in[5] mask — unused by the model
    const float* x_p     = (const float*)d_in[6];
    const float* A_p     = (const float*)d_in[7];
    const float* self_g  = (const float*)d_in[8];
    const float* self_t  = (const float*)d_in[9];
    const float* other_g1 = (const float*)d_in[10];
    const float* other_t1 = (const float*)d_in[11];
    const float* other_g2 = (const float*)d_in[12];
    const float* other_t2 = (const float*)d_in[13];
    const float* W_l1a   = (const float*)d_in[14];
    const float* b_l1a   = (const float*)d_in[15];
    const float* W_l1b   = (const float*)d_in[16];
    const float* b_l1b   = (const float*)d_in[17];
    const float* W_l2    = (const float*)d_in[18];
    const float* b_l2    = (const float*)d_in[19];
    const float* Wd1     = (const float*)d_in[20];
    const float* bd1     = (const float*)d_in[21];
    const float* Wd2     = (const float*)d_in[22];
    const float* bd2     = (const float*)d_in[23];
    const float* Wo      = (const float*)d_in[24];
    const float* bo      = (const float*)d_in[25];
    float* out = (float*)d_out;

    k_init<<<1, 512>>>(b_l1a, b_l1b, b_l2, W_l2);

    {
        int tot = NB * NN * 288;
        k_stage_a<<<(tot + 255) / 256, 256>>>(x_n, self_g, self_t, other_g1,
                                              other_t1, other_g2, other_t2,
                                              W_l1a, W_l1b);
    }
    {
        int tot = NB * NP_ * 32;
        k_stage_p<<<(tot + 255) / 256, 256>>>(x_p, W_l1a);
    }

    k_gemm_l1<<<dim3(5, 16, NB), 256>>>(A_n);
    k_gemm_p<<<dim3(1, 8, NB), 256>>>(A_p);

    {
        int tot = NB * NN * 352;
        k_stage_c<<<(tot + 255) / 256, 256>>>(W_l2);
    }

    k_gemm_l2<<<dim3(7, 16, NB), 256>>>(A_n, A_n_ts, A_n_cs, A_s);

    k_dense<<<1, 128>>>(Wd1, bd1, Wd2, bd2, Wo, bo, out);
}

// round 13
// speedup vs baseline: 1.0037x; 1.0013x over previous
#include <cuda_runtime.h>
#include <cuda_bf16.h>

// Problem constants
// B=8, N=2048, NP=1024, FN=6, FS=3, H=32, NQ=128
#define NB   8
#define NN   2048
#define NP_  1024
#define H_   32

// ---------------- scratch (device globals; no allocation) ----------------
__device__ float g_Ycat[NB * NN * 288];   // layer-1 right operands (9 x 32 cols)
__device__ float g_Z   [NB * NN * 288];   // layer-1 relu outputs x11,x12,x13,xb0..xb5
__device__ float g_Yp  [NB * NP_ * 32];   // x_p @ W_l1a[3]
__device__ float g_U   [NB * NN * 352];   // layer-2 right operands (raw order)
__device__ float g_pooled[NB * 32];       // sum over nodes of relu(A_p branch)
__device__ float g_pool2 [NB * 352];      // layer-2 pooled results (raw order)
__device__ float g_biasL1[288];
__device__ float g_biasP [32];
__device__ float g_biasL2[352];
__device__ float g_wsum10[32];

// Ucat segment j (cols 32j..32j+31 of raw layout, j<8) <-> layer-2 pair index
__device__ const int c_pmap[8] = {0, 4, 5, 6, 7, 8, 9, 10};
// raw offset of pooled2[pair i] inside g_pool2 row
__device__ const int c_off[11] = {0, 256, 288, 320, 32, 64, 96, 128, 160, 192, 224};

// ---------------- packed f32x2 helpers ----------------
__device__ __forceinline__ unsigned long long packdup(float x) {
    unsigned long long r;
    unsigned int xi = __float_as_uint(x);
    asm("mov.b64 %0, {%1, %2};" : "=l"(r) : "r"(xi), "r"(xi));
    return r;
}
__device__ __forceinline__ void fma2(unsigned long long &d,
                                     unsigned long long a,
                                     unsigned long long b) {
    asm("fma.rn.f32x2 %0, %1, %2, %0;" : "+l"(d) : "l"(a), "l"(b));
}
__device__ __forceinline__ float2 unpack2(unsigned long long v) {
    unsigned int lo, hi;
    asm("mov.b64 {%0, %1}, %2;" : "=r"(lo), "=r"(hi) : "l"(v));
    float2 f;
    f.x = __uint_as_float(lo);
    f.y = __uint_as_float(hi);
    return f;
}

// ---------------- init: zero accumulators, prepare bias vectors ----------------
__global__ void k_init(const float* __restrict__ b1a, const float* __restrict__ b1b,
                       const float* __restrict__ b2,  const float* __restrict__ W2) {
    int t = threadIdx.x;  // 512 threads, one block
    for (int i = t; i < NB * 352; i += 512) g_pool2[i] = 0.f;
    for (int i = t; i < NB * 32;  i += 512) g_pooled[i] = 0.f;
    for (int i = t; i < 288; i += 512)
        g_biasL1[i] = (i < 96) ? b1a[(i >> 5) * 32 + (i & 31)]
                               : b1b[((i - 96) >> 5) * 32 + (i & 31)];
    for (int i = t; i < 32; i += 512) g_biasP[i] = b1a[3 * 32 + i];
    for (int i = t; i < 352; i += 512) {
        int pair = (i < 256) ? c_pmap[i >> 5] : 1 + ((i - 256) >> 5);
        g_biasL2[i] = b2[pair * 32 + (i & 31)];
    }
    for (int i = t; i < 32; i += 512) {
        float s = 0.f;
        for (int k = 0; k < 32; k++) s += W2[(10 * 32 + k) * 32 + i];
        g_wsum10[i] = s;
    }
}

// ---------------- stage A: layer-1 right operands ----------------
__global__ void k_stage_a(const float* __restrict__ xn,
                          const float* __restrict__ sg,  const float* __restrict__ st,
                          const float* __restrict__ og1, const float* __restrict__ ot1,
                          const float* __restrict__ og2, const float* __restrict__ ot2,
                          const float* __restrict__ Wa,  const float* __restrict__ Wb) {
    int idx = blockIdx.x * blockDim.x + threadIdx.x;
    if (idx >= NB * NN * 288) return;
    int c = idx % 288;
    int bn = idx / 288;
    int h = c & 31;
    float acc = 0.f;
    if (c < 96) {
        int j = c >> 5;
        const float* xr = xn + (size_t)bn * 6;
#pragma unroll
        for (int f = 0; f < 6; f++) acc += xr[f] * Wa[(j * 6 + f) * 32 + h];
    } else {
        int i = (c - 96) >> 5;
        const float* fp;
        switch (i) {
            case 0: fp = sg;  break;
            case 1: fp = st;  break;
            case 2: fp = og1; break;
            case 3: fp = ot1; break;
            case 4: fp = og2; break;
            default: fp = ot2;
        }
        const float* xr = fp + (size_t)bn * 3;
#pragma unroll
        for (int f = 0; f < 3; f++) acc += xr[f] * Wb[(i * 3 + f) * 32 + h];
    }
    g_Ycat[idx] = acc;
}

__global__ void k_stage_p(const float* __restrict__ xp, const float* __restrict__ Wa) {
    int idx = blockIdx.x * blockDim.x + threadIdx.x;
    if (idx >= NB * NP_ * 32) return;
    int h = idx & 31;
    int bn = idx >> 5;
    const float* xr = xp + (size_t)bn * 6;
    float acc = 0.f;
#pragma unroll
    for (int f = 0; f < 6; f++) acc += xr[f] * Wa[(3 * 6 + f) * 32 + h];
    g_Yp[idx] = acc;
}

// ---------------- stage C: layer-2 right operands U = Z @ W_l2 ----------------
__global__ void k_stage_c(const float* __restrict__ W2) {
    int idx = blockIdx.x * blockDim.x + threadIdx.x;
    if (idx >= NB * NN * 352) return;
    int c = idx % 352;
    int bn = idx / 352;
    int b = bn >> 11;
    int n = bn & 2047;
    int h = c & 31;
    int pair = (c < 256) ? c_pmap[c >> 5] : 1 + ((c - 256) >> 5);
    float acc;
    if (pair == 10) {
        acc = g_pooled[b * 32 + (n >> 6)] * g_wsum10[h];
    } else {
        int zbase;
        if (pair == 0) zbase = 0;
        else if (pair <= 2) zbase = 32;        // x12
        else if (pair == 3) zbase = 64;        // x13
        else zbase = 96 + 32 * (pair - 4);     // xb[pair-4]
        const float* zr = g_Z + (size_t)bn * 288 + zbase;
        const float* wr = W2 + (pair * 32) * 32 + h;
        acc = 0.f;
#pragma unroll
        for (int k = 0; k < 32; k++) acc += zr[k] * wr[k * 32];
    }
    g_U[idx] = acc;
}

// ---------------- tiled GEMM: C = relu(A @ B + bias), opt. row-sum reduce ----------------
#define BM 128
#define BN 64
#define BK 16

template <bool REDUCE>
__device__ __forceinline__ void gemm_body(
    const float* __restrict__ gA,    // M x K, lda = K (batch-adjusted)
    const float* __restrict__ gB,    // K x *, ldb (batch- and column-base-adjusted)
    float* __restrict__ gC,          // ldc (WRITE path)
    float* __restrict__ pool,        // batch-adjusted pool row (REDUCE path)
    const float* __restrict__ bias,  // indexed by n0 + local col
    int M, int K, int Ncols, int ldb, int ldc, int n0) {
    __shared__ float As[BK][BM + 4];
    __shared__ float Bs[BK][BN];
    __shared__ float red[16][64];

    int lid = threadIdx.x;        // 256 threads
    int tx = lid & 15;            // n-direction (x4 cols)
    int ty = lid >> 4;            // m-direction (x8 rows)
    int m0 = blockIdx.y * BM;

    unsigned long long acc[4][4];
#pragma unroll
    for (int i = 0; i < 4; i++)
#pragma unroll
        for (int j = 0; j < 4; j++) acc[i][j] = 0ull;

    int arow = lid >> 2;
    int ac4 = lid & 3;
    int brow = lid >> 4;
    int bcol = (lid & 15) << 2;
    bool bvalid = (n0 + bcol) < Ncols;

    for (int k0 = 0; k0 < K; k0 += BK) {
        // A tile -> transposed into shared
#pragma unroll
        for (int r = 0; r < 2; r++) {
            int row = arow + r * 64;
            float4 v = *reinterpret_cast<const float4*>(
                gA + (size_t)(m0 + row) * K + k0 + (ac4 << 2));
            As[(ac4 << 2) + 0][row] = v.x;
            As[(ac4 << 2) + 1][row] = v.y;
            As[(ac4 << 2) + 2][row] = v.z;
            As[(ac4 << 2) + 3][row] = v.w;
        }
        float4 bv = make_float4(0.f, 0.f, 0.f, 0.f);
        if (bvalid)
            bv = *reinterpret_cast<const float4*>(
                gB + (size_t)(k0 + brow) * ldb + n0 + bcol);
        *reinterpret_cast<float4*>(&Bs[brow][bcol]) = bv;
        __syncthreads();

#pragma unroll
        for (int k = 0; k < BK; k++) {
            unsigned long long a2[4];
#pragma unroll
            for (int ii = 0; ii < 4; ii++)
                a2[ii] = *reinterpret_cast<const unsigned long long*>(
                    &As[k][ty * 8 + (ii << 1)]);
            float4 bq = *reinterpret_cast<const float4*>(&Bs[k][tx << 2]);
            unsigned long long b2[4];
            b2[0] = packdup(bq.x);
            b2[1] = packdup(bq.y);
            b2[2] = packdup(bq.z);
            b2[3] = packdup(bq.w);
#pragma unroll
            for (int ii = 0; ii < 4; ii++)
#pragma unroll
                for (int j = 0; j < 4; j++) fma2(acc[ii][j], a2[ii], b2[j]);
        }
        __syncthreads();
    }

    // epilogue
    float cv[8][4];
#pragma unroll
    for (int ii = 0; ii < 4; ii++)
#pragma unroll
        for (int j = 0; j < 4; j++) {
            float2 f = unpack2(acc[ii][j]);
            cv[2 * ii + 0][j] = f.x;
            cv[2 * ii + 1][j] = f.y;
        }
    float bb[4];
#pragma unroll
    for (int j = 0; j < 4; j++) {
        int n = n0 + (tx << 2) + j;
        bb[j] = (n < Ncols) ? bias[n] : 0.f;
    }
    if (!REDUCE) {
        if (bvalid) {
#pragma unroll
            for (int r = 0; r < 8; r++) {
                float4 o;
                o.x = fmaxf(cv[r][0] + bb[0], 0.f);
                o.y = fmaxf(cv[r][1] + bb[1], 0.f);
                o.z = fmaxf(cv[r][2] + bb[2], 0.f);
                o.w = fmaxf(cv[r][3] + bb[3], 0.f);
                *reinterpret_cast<float4*>(
                    gC + (size_t)(m0 + ty * 8 + r) * ldc + n0 + (tx << 2)) = o;
            }
        }
    } else {
        float ps[4] = {0.f, 0.f, 0.f, 0.f};
#pragma unroll
        for (int r = 0; r < 8; r++)
#pragma unroll
            for (int j = 0; j < 4; j++) ps[j] += fmaxf(cv[r][j] + bb[j], 0.f);
#pragma unroll
        for (int j = 0; j < 4; j++) red[ty][(tx << 2) + j] = ps[j];
        __syncthreads();
        if (lid < 64) {
            float s = 0.f;
#pragma unroll
            for (int t = 0; t < 16; t++) s += red[t][lid];
            if (n0 + lid < Ncols) atomicAdd(&pool[n0 + lid], s);
        }
    }
}

// layer-1 main graph: Z = relu(A_n @ Ycat + biasL1)   grid (5,16,8)
__global__ void __launch_bounds__(256) k_gemm_l1(const float* __restrict__ An) {
    int b = blockIdx.z;
    gemm_body<false>(An + (size_t)b * NN * NN,
                     g_Ycat + (size_t)b * NN * 288,
                     g_Z + (size_t)b * NN * 288,
                     nullptr, g_biasL1,
                     NN, NN, 288, 288, 288, blockIdx.x * BN);
}

// A_p branch: pooled = sum_n relu(A_p @ Yp + biasP)   grid (1,8,8)
__global__ void __launch_bounds__(256) k_gemm_p(const float* __restrict__ Ap) {
    int b = blockIdx.z;
    gemm_body<true>(Ap + (size_t)b * NP_ * NP_,
                    g_Yp + (size_t)b * NP_ * 32,
                    nullptr, g_pooled + b * 32, g_biasP,
                    NP_, NP_, 32, 32, 0, 0);
}

// layer-2 (all 11 pairs): pool2 += sum_n relu(A @ U + biasL2)   grid (7,16,8)
__global__ void __launch_bounds__(256) k_gemm_l2(const float* __restrict__ An,
                                                 const float* __restrict__ Ats,
                                                 const float* __restrict__ Acs,
                                                 const float* __restrict__ Asl) {
    int b = blockIdx.z;
    int slot = blockIdx.x;
    const float* A;
    int n0, bofs, ncols;
    if (slot < 4) {
        A = An; n0 = slot * BN; bofs = 0; ncols = 256;
    } else {
        A = (slot == 4) ? Ats : ((slot == 5) ? Acs : Asl);
        n0 = 0; bofs = 256 + 32 * (slot - 4); ncols = 32;
    }
    gemm_body<true>(A + (size_t)b * NN * NN,
                    g_U + (size_t)b * NN * 352 + bofs,
                    nullptr, g_pool2 + b * 352 + bofs, g_biasL2 + bofs,
                    NN, NN, ncols, 352, 0, n0);
}

// ---------------- dense head ----------------
__global__ void k_dense(const float* __restrict__ Wd1, const float* __restrict__ bd1,
                        const float* __restrict__ Wd2, const float* __restrict__ bd2,
                        const float* __restrict__ Wo,  const float* __restrict__ bo,
                        float* __restrict__ out) {
    __shared__ float sq[352];
    __shared__ float h1[128];
    __shared__ float h2[128];
    __shared__ float rbuf[128];
    int t = threadIdx.x;  // 128 threads
    for (int b = 0; b < NB; b++) {
        for (int i = t; i < 352; i += 128) {
            int p = i >> 5;
            sq[i] = g_pool2[b * 352 + c_off[p] + (i & 31)];
        }
        __syncthreads();
        float acc = bd1[t];
        for (int k = 0; k < 352; k++) acc += sq[k] * Wd1[k * 128 + t];
        h1[t] = fmaxf(acc, 0.f);
        __syncthreads();
        float a2 = bd2[t];
        for (int k = 0; k < 128; k++) a2 += h1[k] * Wd2[k * 128 + t];
        h2[t] = fmaxf(a2, 0.f);
        __syncthreads();
        rbuf[t] = h2[t] * Wo[t];
        __syncthreads();
        for (int w = 64; w > 0; w >>= 1) {
            if (t < w) rbuf[t] += rbuf[t + w];
            __syncthreads();
        }
        if (t == 0) out[b] = rbuf[0] + bo[0];
        __syncthreads();
    }
}

// ---------------- launch ----------------
extern "C" void kernel_launch(void* const* d_in, const int* in_sizes, int n_in,
                              void* d_out, int out_size) {
    const float* x_n     = (const float*)d_in[0];
    const float* A_n     = (const float*)d_in[1];
    const float* A_s     = (const float*)d_in[2];
    const float* A_n_ts  = (const float*)d_in[3];
    const float* A_n_cs  = (const float*)d_in[4];
    // d_in[5] mask — unused by the model
    const float* x_p     = (const float*)d_in[6];
    const float* A_p     = (const float*)d_in[7];
    const float* self_g  = (const float*)d_in[8];
    const float* self_t  = (const float*)d_in[9];
    const float* other_g1 = (const float*)d_in[10];
    const float* other_t1 = (const float*)d_in[11];
    const float* other_g2 = (const float*)d_in[12];
    const float* other_t2 = (const float*)d_in[13];
    const float* W_l1a   = (const float*)d_in[14];
    const float* b_l1a   = (const float*)d_in[15];
    const float* W_l1b   = (const float*)d_in[16];
    const float* b_l1b   = (const float*)d_in[17];
    const float* W_l2    = (const float*)d_in[18];
    const float* b_l2    = (const float*)d_in[19];
    const float* Wd1     = (const float*)d_in[20];
    const float* bd1     = (const float*)d_in[21];
    const float* Wd2     = (const float*)d_in[22];
    const float* bd2     = (const float*)d_in[23];
    const float* Wo      = (const float*)d_in[24];
    const float* bo      = (const float*)d_in[25];
    float* out = (float*)d_out;

    k_init<<<1, 512>>>(b_l1a, b_l1b, b_l2, W_l2);

    {
        int tot = NB * NN * 288;
        k_stage_a<<<(tot + 255) / 256, 256>>>(x_n, self_g, self_t, other_g1,
                                              other_t1, other_g2, other_t2,
                                              W_l1a, W_l1b);
    }
    {
        int tot = NB * NP_ * 32;
        k_stage_p<<<(tot + 255) / 256, 256>>>(x_p, W_l1a);
    }

    k_gemm_l1<<<dim3(5, 16, NB), 256>>>(A_n);
    k_gemm_p<<<dim3(1, 8, NB), 256>>>(A_p);

    {
        int tot = NB * NN * 352;
        k_stage_c<<<(tot + 255) / 256, 256>>>(W_l2);
    }

    k_gemm_l2<<<dim3(7, 16, NB), 256>>>(A_n, A_n_ts, A_n_cs, A_s);

    k_dense<<<1, 128>>>(Wd1, bd1, Wd2, bd2, Wo, bo, out);
}

// round 14
// speedup vs baseline: 1.0103x; 1.0066x over previous
#include <cuda_runtime.h>
#include <cuda_bf16.h>

// Problem constants
// B=8, N=2048, NP=1024, FN=6, FS=3, H=32, NQ=128
#define NB   8
#define NN   2048
#define NP_  1024
#define H_   32

// ---------------- scratch (device globals; no allocation) ----------------
__device__ float g_Ycat[NB * NN * 288];   // layer-1 right operands (9 x 32 cols)
__device__ float g_Z   [NB * NN * 288];   // layer-1 relu outputs x11,x12,x13,xb0..xb5
__device__ float g_Yp  [NB * NP_ * 32];   // x_p @ W_l1a[3]
__device__ float g_U   [NB * NN * 352];   // layer-2 right operands (raw order)
__device__ float g_pooled[NB * 32];       // sum over nodes of relu(A_p branch)
__device__ float g_pool2 [NB * 352];      // layer-2 pooled results (raw order)
__device__ float g_biasL1[288];
__device__ float g_biasP [32];
__device__ float g_biasL2[352];
__device__ float g_wsum10[32];

// Ucat segment j (cols 32j..32j+31 of raw layout, j<8) <-> layer-2 pair index
__device__ const int c_pmap[8] = {0, 4, 5, 6, 7, 8, 9, 10};
// raw offset of pooled2[pair i] inside g_pool2 row
__device__ const int c_off[11] = {0, 256, 288, 320, 32, 64, 96, 128, 160, 192, 224};

// ---------------- packed f32x2 helpers ----------------
__device__ __forceinline__ unsigned long long packdup(float x) {
    unsigned long long r;
    unsigned int xi = __float_as_uint(x);
    asm("mov.b64 %0, {%1, %2};" : "=l"(r) : "r"(xi), "r"(xi));
    return r;
}
__device__ __forceinline__ void fma2(unsigned long long &d,
                                     unsigned long long a,
                                     unsigned long long b) {
    asm("fma.rn.f32x2 %0, %1, %2, %0;" : "+l"(d) : "l"(a), "l"(b));
}
__device__ __forceinline__ float2 unpack2(unsigned long long v) {
    unsigned int lo, hi;
    asm("mov.b64 {%0, %1}, %2;" : "=r"(lo), "=r"(hi) : "l"(v));
    float2 f;
    f.x = __uint_as_float(lo);
    f.y = __uint_as_float(hi);
    return f;
}

// ---------------- init: zero accumulators, prepare bias vectors ----------------
__global__ void k_init(const float* __restrict__ b1a, const float* __restrict__ b1b,
                       const float* __restrict__ b2,  const float* __restrict__ W2) {
    int t = threadIdx.x;  // 512 threads, one block
    for (int i = t; i < NB * 352; i += 512) g_pool2[i] = 0.f;
    for (int i = t; i < NB * 32;  i += 512) g_pooled[i] = 0.f;
    for (int i = t; i < 288; i += 512)
        g_biasL1[i] = (i < 96) ? b1a[(i >> 5) * 32 + (i & 31)]
                               : b1b[((i - 96) >> 5) * 32 + (i & 31)];
    for (int i = t; i < 32; i += 512) g_biasP[i] = b1a[3 * 32 + i];
    for (int i = t; i < 352; i += 512) {
        int pair = (i < 256) ? c_pmap[i >> 5] : 1 + ((i - 256) >> 5);
        g_biasL2[i] = b2[pair * 32 + (i & 31)];
    }
    for (int i = t; i < 32; i += 512) {
        float s = 0.f;
        for (int k = 0; k < 32; k++) s += W2[(10 * 32 + k) * 32 + i];
        g_wsum10[i] = s;
    }
}

// ---------------- stage A: layer-1 right operands ----------------
__global__ void k_stage_a(const float* __restrict__ xn,
                          const float* __restrict__ sg,  const float* __restrict__ st,
                          const float* __restrict__ og1, const float* __restrict__ ot1,
                          const float* __restrict__ og2, const float* __restrict__ ot2,
                          const float* __restrict__ Wa,  const float* __restrict__ Wb) {
    int idx = blockIdx.x * blockDim.x + threadIdx.x;
    if (idx >= NB * NN * 288) return;
    int c = idx % 288;
    int bn = idx / 288;
    int h = c & 31;
    float acc = 0.f;
    if (c < 96) {
        int j = c >> 5;
        const float* xr = xn + (size_t)bn * 6;
#pragma unroll
        for (int f = 0; f < 6; f++) acc += xr[f] * Wa[(j * 6 + f) * 32 + h];
    } else {
        int i = (c - 96) >> 5;
        const float* fp;
        switch (i) {
            case 0: fp = sg;  break;
            case 1: fp = st;  break;
            case 2: fp = og1; break;
            case 3: fp = ot1; break;
            case 4: fp = og2; break;
            default: fp = ot2;
        }
        const float* xr = fp + (size_t)bn * 3;
#pragma unroll
        for (int f = 0; f < 3; f++) acc += xr[f] * Wb[(i * 3 + f) * 32 + h];
    }
    g_Ycat[idx] = acc;
}

__global__ void k_stage_p(const float* __restrict__ xp, const float* __restrict__ Wa) {
    int idx = blockIdx.x * blockDim.x + threadIdx.x;
    if (idx >= NB * NP_ * 32) return;
    int h = idx & 31;
    int bn = idx >> 5;
    const float* xr = xp + (size_t)bn * 6;
    float acc = 0.f;
#pragma unroll
    for (int f = 0; f < 6; f++) acc += xr[f] * Wa[(3 * 6 + f) * 32 + h];
    g_Yp[idx] = acc;
}

// ---------------- stage C: layer-2 right operands U = Z @ W_l2 ----------------
__global__ void k_stage_c(const float* __restrict__ W2) {
    int idx = blockIdx.x * blockDim.x + threadIdx.x;
    if (idx >= NB * NN * 352) return;
    int c = idx % 352;
    int bn = idx / 352;
    int b = bn >> 11;
    int n = bn & 2047;
    int h = c & 31;
    int pair = (c < 256) ? c_pmap[c >> 5] : 1 + ((c - 256) >> 5);
    float acc;
    if (pair == 10) {
        acc = g_pooled[b * 32 + (n >> 6)] * g_wsum10[h];
    } else {
        int zbase;
        if (pair == 0) zbase = 0;
        else if (pair <= 2) zbase = 32;        // x12
        else if (pair == 3) zbase = 64;        // x13
        else zbase = 96 + 32 * (pair - 4);     // xb[pair-4]
        const float* zr = g_Z + (size_t)bn * 288 + zbase;
        const float* wr = W2 + (pair * 32) * 32 + h;
        acc = 0.f;
#pragma unroll
        for (int k = 0; k < 32; k++) acc += zr[k] * wr[k * 32];
    }
    g_U[idx] = acc;
}

// ---------------- tiled GEMM: C = relu(A @ B + bias), opt. row-sum reduce ----------------
#define BM 128
#define BN 64
#define BK 16

template <bool REDUCE>
__device__ __forceinline__ void gemm_body(
    const float* __restrict__ gA,    // M x K, lda = K (batch-adjusted)
    const float* __restrict__ gB,    // K x *, ldb (batch- and column-base-adjusted)
    float* __restrict__ gC,          // ldc (WRITE path)
    float* __restrict__ pool,        // batch-adjusted pool row (REDUCE path)
    const float* __restrict__ bias,  // indexed by n0 + local col
    int M, int K, int Ncols, int ldb, int ldc, int n0) {
    __shared__ float As[BK][BM + 4];
    __shared__ float Bs[BK][BN];
    __shared__ float red[16][64];

    int lid = threadIdx.x;        // 256 threads
    int tx = lid & 15;            // n-direction (x4 cols)
    int ty = lid >> 4;            // m-direction (x8 rows)
    int m0 = blockIdx.y * BM;

    unsigned long long acc[4][4];
#pragma unroll
    for (int i = 0; i < 4; i++)
#pragma unroll
        for (int j = 0; j < 4; j++) acc[i][j] = 0ull;

    int arow = lid >> 2;
    int ac4 = lid & 3;
    int brow = lid >> 4;
    int bcol = (lid & 15) << 2;
    bool bvalid = (n0 + bcol) < Ncols;

    for (int k0 = 0; k0 < K; k0 += BK) {
        // A tile -> transposed into shared
#pragma unroll
        for (int r = 0; r < 2; r++) {
            int row = arow + r * 64;
            float4 v = *reinterpret_cast<const float4*>(
                gA + (size_t)(m0 + row) * K + k0 + (ac4 << 2));
            As[(ac4 << 2) + 0][row] = v.x;
            As[(ac4 << 2) + 1][row] = v.y;
            As[(ac4 << 2) + 2][row] = v.z;
            As[(ac4 << 2) + 3][row] = v.w;
        }
        float4 bv = make_float4(0.f, 0.f, 0.f, 0.f);
        if (bvalid)
            bv = *reinterpret_cast<const float4*>(
                gB + (size_t)(k0 + brow) * ldb + n0 + bcol);
        *reinterpret_cast<float4*>(&Bs[brow][bcol]) = bv;
        __syncthreads();

#pragma unroll
        for (int k = 0; k < BK; k++) {
            unsigned long long a2[4];
#pragma unroll
            for (int ii = 0; ii < 4; ii++)
                a2[ii] = *reinterpret_cast<const unsigned long long*>(
                    &As[k][ty * 8 + (ii << 1)]);
            float4 bq = *reinterpret_cast<const float4*>(&Bs[k][tx << 2]);
            unsigned long long b2[4];
            b2[0] = packdup(bq.x);
            b2[1] = packdup(bq.y);
            b2[2] = packdup(bq.z);
            b2[3] = packdup(bq.w);
#pragma unroll
            for (int ii = 0; ii < 4; ii++)
#pragma unroll
                for (int j = 0; j < 4; j++) fma2(acc[ii][j], a2[ii], b2[j]);
        }
        __syncthreads();
    }

    // epilogue
    float cv[8][4];
#pragma unroll
    for (int ii = 0; ii < 4; ii++)
#pragma unroll
        for (int j = 0; j < 4; j++) {
            float2 f = unpack2(acc[ii][j]);
            cv[2 * ii + 0][j] = f.x;
            cv[2 * ii + 1][j] = f.y;
        }
    float bb[4];
#pragma unroll
    for (int j = 0; j < 4; j++) {
        int n = n0 + (tx << 2) + j;
        bb[j] = (n < Ncols) ? bias[n] : 0.f;
    }
    if (!REDUCE) {
        if (bvalid) {
#pragma unroll
            for (int r = 0; r < 8; r++) {
                float4 o;
                o.x = fmaxf(cv[r][0] + bb[0], 0.f);
                o.y = fmaxf(cv[r][1] + bb[1], 0.f);
                o.z = fmaxf(cv[r][2] + bb[2], 0.f);
                o.w = fmaxf(cv[r][3] + bb[3], 0.f);
                *reinterpret_cast<float4*>(
                    gC + (size_t)(m0 + ty * 8 + r) * ldc + n0 + (tx << 2)) = o;
            }
        }
    } else {
        float ps[4] = {0.f, 0.f, 0.f, 0.f};
#pragma unroll
        for (int r = 0; r < 8; r++)
#pragma unroll
            for (int j = 0; j < 4; j++) ps[j] += fmaxf(cv[r][j] + bb[j], 0.f);
#pragma unroll
        for (int j = 0; j < 4; j++) red[ty][(tx << 2) + j] = ps[j];
        __syncthreads();
        if (lid < 64) {
            float s = 0.f;
#pragma unroll
            for (int t = 0; t < 16; t++) s += red[t][lid];
            if (n0 + lid < Ncols) atomicAdd(&pool[n0 + lid], s);
        }
    }
}

// layer-1 main graph: Z = relu(A_n @ Ycat + biasL1)   grid (5,16,8)
__global__ void __launch_bounds__(256) k_gemm_l1(const float* __restrict__ An) {
    int b = blockIdx.z;
    gemm_body<false>(An + (size_t)b * NN * NN,
                     g_Ycat + (size_t)b * NN * 288,
                     g_Z + (size_t)b * NN * 288,
                     nullptr, g_biasL1,
                     NN, NN, 288, 288, 288, blockIdx.x * BN);
}

// A_p branch: pooled = sum_n relu(A_p @ Yp + biasP)   grid (1,8,8)
__global__ void __launch_bounds__(256) k_gemm_p(const float* __restrict__ Ap) {
    int b = blockIdx.z;
    gemm_body<true>(Ap + (size_t)b * NP_ * NP_,
                    g_Yp + (size_t)b * NP_ * 32,
                    nullptr, g_pooled + b * 32, g_biasP,
                    NP_, NP_, 32, 32, 0, 0);
}

// layer-2 (all 11 pairs): pool2 += sum_n relu(A @ U + biasL2)   grid (7,16,8)
__global__ void __launch_bounds__(256) k_gemm_l2(const float* __restrict__ An,
                                                 const float* __restrict__ Ats,
                                                 const float* __restrict__ Acs,
                                                 const float* __restrict__ Asl) {
    int b = blockIdx.z;
    int slot = blockIdx.x;
    const float* A;
    int n0, bofs, ncols;
    if (slot < 4) {
        A = An; n0 = slot * BN; bofs = 0; ncols = 256;
    } else {
        A = (slot == 4) ? Ats : ((slot == 5) ? Acs : Asl);
        n0 = 0; bofs = 256 + 32 * (slot - 4); ncols = 32;
    }
    gemm_body<true>(A + (size_t)b * NN * NN,
                    g_U + (size_t)b * NN * 352 + bofs,
                    nullptr, g_pool2 + b * 352 + bofs, g_biasL2 + bofs,
                    NN, NN, ncols, 352, 0, n0);
}

// ---------------- dense head ----------------
__global__ void k_dense(const float* __restrict__ Wd1, const float* __restrict__ bd1,
                        const float* __restrict__ Wd2, const float* __restrict__ bd2,
                        const float* __restrict__ Wo,  const float* __restrict__ bo,
                        float* __restrict__ out) {
    __shared__ float sq[352];
    __shared__ float h1[128];
    __shared__ float h2[128];
    __shared__ float rbuf[128];
    int t = threadIdx.x;  // 128 threads
    for (int b = 0; b < NB; b++) {
        for (int i = t; i < 352; i += 128) {
            int p = i >> 5;
            sq[i] = g_pool2[b * 352 + c_off[p] + (i & 31)];
        }
        __syncthreads();
        float acc = bd1[t];
        for (int k = 0; k < 352; k++) acc += sq[k] * Wd1[k * 128 + t];
        h1[t] = fmaxf(acc, 0.f);
        __syncthreads();
        float a2 = bd2[t];
        for (int k = 0; k < 128; k++) a2 += h1[k] * Wd2[k * 128 + t];
        h2[t] = fmaxf(a2, 0.f);
        __syncthreads();
        rbuf[t] = h2[t] * Wo[t];
        __syncthreads();
        for (int w = 64; w > 0; w >>= 1) {
            if (t < w) rbuf[t] += rbuf[t + w];
            __syncthreads();
        }
        if (t == 0) out[b] = rbuf[0] + bo[0];
        __syncthreads();
    }
}

// ---------------- launch ----------------
extern "C" void kernel_launch(void* const* d_in, const int* in_sizes, int n_in,
                              void* d_out, int out_size) {
    const float* x_n     = (const float*)d_in[0];
    const float* A_n     = (const float*)d_in[1];
    const float* A_s     = (const float*)d_in[2];
    const float* A_n_ts  = (const float*)d_in[3];
    const float* A_n_cs  = (const float*)d_in[4];
    // d_in[5] mask — unused by the model
    const float* x_p     = (const float*)d_in[6];
    const float* A_p     = (const float*)d_in[7];
    const float* self_g  = (const float*)d_in[8];
    const float* self_t  = (const float*)d_in[9];
    const float* other_g1 = (const float*)d_in[10];
    const float* other_t1 = (const float*)d_in[11];
    const float* other_g2 = (const float*)d_in[12];
    const float* other_t2 = (const float*)d_in[13];
    const float* W_l1a   = (const float*)d_in[14];
    const float* b_l1a   = (const float*)d_in[15];
    const float* W_l1b   = (const float*)d_in[16];
    const float* b_l1b   = (const float*)d_in[17];
    const float* W_l2    = (const float*)d_in[18];
    const float* b_l2    = (const float*)d_in[19];
    const float* Wd1     = (const float*)d_in[20];
    const float* bd1     = (const float*)d_in[21];
    const float* Wd2     = (const float*)d_in[22];
    const float* bd2     = (const float*)d_in[23];
    const float* Wo      = (const float*)d_in[24];
    const float* bo      = (const float*)d_in[25];
    float* out = (float*)d_out;

    k_init<<<1, 512>>>(b_l1a, b_l1b, b_l2, W_l2);

    {
        int tot = NB * NN * 288;
        k_stage_a<<<(tot + 255) / 256, 256>>>(x_n, self_g, self_t, other_g1,
                                              other_t1, other_g2, other_t2,
                                              W_l1a, W_l1b);
    }
    {
        int tot = NB * NP_ * 32;
        k_stage_p<<<(tot + 255) / 256, 256>>>(x_p, W_l1a);
    }

    k_gemm_l1<<<dim3(5, 16, NB), 256>>>(A_n);
    k_gemm_p<<<dim3(1, 8, NB), 256>>>(A_p);

    {
        int tot = NB * NN * 352;
        k_stage_c<<<(tot + 255) / 256, 256>>>(W_l2);
    }

    k_gemm_l2<<<dim3(7, 16, NB), 256>>>(A_n, A_n_ts, A_n_cs, A_s);

    k_dense<<<1, 128>>>(Wd1, bd1, Wd2, bd2, Wo, bo, out);
}